// round 3
// baseline (speedup 1.0000x reference)
#include <cuda_runtime.h>
#include <math.h>

// ---------------- problem constants ----------------
#define NB   8
#define ND   768
#define NCH  3
#define NMIX 5
#define NS   10
#define H    10
#define PI2f 6.2831853071795864769f
// C = -0.5*(2pi)^2 * log2(e)  (fold exp->exp2)
#define CEXP (-28.47813296f)
#define ZITTER 1e-4f

// ---------------- device scratch ----------------
__device__ float2 g_tab[NB * NCH * NMIX * ND];   // (cos,sin)(2pi*mu_m*x_j)
__device__ float2 g_tabY[NB * NCH * NMIX * ND];  // y-premultiplied
__device__ float  g_xr[NB * NCH * ND];
#define NSEG 8
#define JSEG 96
__device__ float  g_fpart[NSEG][NB * ND * NCH * NMIX];
__device__ float  g_w[NB * NCH * NMIX];

__device__ __forceinline__ float ex2f(float x) {
    float y;
    asm("ex2.approx.ftz.f32 %0, %1;" : "=f"(y) : "f"(x));
    return y;
}

// ============ Kernel 0: trig tables (+ y-premultiplied) ============
__global__ void k0_tables(const float* __restrict__ xc,
                          const float* __restrict__ yc,
                          const float* __restrict__ mu) {
    int bc = blockIdx.x;
    int b = bc / NCH, c = bc % NCH;
    int j = threadIdx.x;
    float x = xc[(b * ND + j) * NCH + c];
    float y = yc[(b * ND + j) * NCH + c];
    g_xr[bc * ND + j] = x;
#pragma unroll
    for (int m = 0; m < NMIX; m++) {
        float s, co;
        sincosf(PI2f * mu[m] * x, &s, &co);
        g_tab [(bc * NMIX + m) * ND + j] = make_float2(co, s);
        g_tabY[(bc * NMIX + m) * ND + j] = make_float2(co * y, s * y);
    }
}

// ============ Kernel 1: feature partials ============
// grid: x = 6 i-tiles * 8 j-segs, y = c, z = b; block = 128
__global__ void __launch_bounds__(128, 8) k1_feature(
        const float* __restrict__ inv_std) {
    __shared__ float  x_sh[JSEG];
    __shared__ float2 tabY[NMIX * JSEG];

    int seg  = blockIdx.x & 7;
    int tile = blockIdx.x >> 3;
    int c = blockIdx.y, b = blockIdx.z;
    int bc = b * NCH + c;
    int tid = threadIdx.x;
    int j0 = seg * JSEG;

    if (tid < JSEG) x_sh[tid] = g_xr[bc * ND + j0 + tid];
    for (int idx = tid; idx < NMIX * JSEG; idx += 128) {
        int m = idx / JSEG, jl = idx % JSEG;
        tabY[idx] = g_tabY[(bc * NMIX + m) * ND + j0 + jl];
    }
    __syncthreads();

    int i = tile * 128 + tid;
    float xi = g_xr[bc * ND + i];
    float ci[NMIX], si[NMIX], am[NMIX], acc[NMIX];
#pragma unroll
    for (int m = 0; m < NMIX; m++) {
        float2 cs = g_tab[(bc * NMIX + m) * ND + i];
        ci[m] = cs.x; si[m] = cs.y;
        float iv = __ldg(&inv_std[m]);
        am[m] = CEXP * iv * iv;
        acc[m] = 0.f;
    }

#pragma unroll 4
    for (int jl = 0; jl < JSEG; jl++) {
        float d = xi - x_sh[jl];
        float t = d * d;
#pragma unroll
        for (int m = 0; m < NMIX; m++) {
            float2 cy = tabY[m * JSEG + jl];
            float e = ex2f(am[m] * t);
            float p = fmaf(si[m], cy.y, ci[m] * cy.x);
            acc[m] = fmaf(e, p, acc[m]);
        }
    }

    int base = ((b * ND + i) * NCH + c) * NMIX;
#pragma unroll
    for (int m = 0; m < NMIX; m++)
        g_fpart[seg][base + m] = acc[m];
}

// ============ Kernel 2: MLP + Gumbel softmax -> mixture weights ============
__global__ void k2_mlp(const float* __restrict__ yc,
                       const float* __restrict__ unif,
                       const float* __restrict__ W1, const float* __restrict__ b1,
                       const float* __restrict__ W2, const float* __restrict__ b2,
                       const float* __restrict__ W3, const float* __restrict__ b3,
                       const float* __restrict__ W4, const float* __restrict__ b4,
                       const float* __restrict__ W5, const float* __restrict__ b5) {
    __shared__ float s_part[256 * 30];
    __shared__ float s_W1[60], s_b1[10];
    __shared__ float s_hm[30];
    __shared__ float s_ha[10], s_hb[10];
    __shared__ float s_ll[15];

    int b = blockIdx.x;
    int tid = threadIdx.x;
    if (tid < 60) s_W1[tid] = W1[tid];
    if (tid < 10) s_b1[tid] = b1[tid];
    __syncthreads();

    float acc30[30];
#pragma unroll
    for (int q = 0; q < 30; q++) acc30[q] = 0.f;

    for (int rep = 0; rep < 3; rep++) {
        int i = tid + rep * 256;
#pragma unroll
        for (int c = 0; c < NCH; c++) {
            int base = ((b * ND + i) * NCH + c) * NMIX;
            float y = yc[(b * ND + i) * NCH + c];
            float tif[6];
#pragma unroll
            for (int m = 0; m < NMIX; m++) {
                float f = ZITTER * y;
#pragma unroll
                for (int s = 0; s < NSEG; s++) f += g_fpart[s][base + m];
                tif[m] = f;
            }
            tif[5] = y;
#pragma unroll
            for (int k = 0; k < H; k++) {
                float h = s_b1[k];
#pragma unroll
                for (int q = 0; q < 6; q++) h = fmaf(tif[q], s_W1[k * 6 + q], h);
                acc30[c * H + k] += fmaxf(h, 0.f);
            }
        }
    }
#pragma unroll
    for (int q = 0; q < 30; q++) s_part[tid * 30 + q] = acc30[q];
    __syncthreads();

    if (tid < 30) {
        float s = 0.f;
        for (int t = 0; t < 256; t++) s += s_part[t * 30 + tid];
        s_hm[tid] = s / (float)ND;
    }
    __syncthreads();

    if (tid < 10) {
        float v = b2[tid];
        for (int q = 0; q < 30; q++) v = fmaf(s_hm[q], W2[tid * 30 + q], v);
        s_ha[tid] = fmaxf(v, 0.f);
    }
    __syncthreads();
    if (tid < 10) {
        float v = b3[tid];
        for (int q = 0; q < 10; q++) v = fmaf(s_ha[q], W3[tid * 10 + q], v);
        s_hb[tid] = fmaxf(v, 0.f);
    }
    __syncthreads();
    if (tid < 10) {
        float v = b4[tid];
        for (int q = 0; q < 10; q++) v = fmaf(s_hb[q], W4[tid * 10 + q], v);
        s_ha[tid] = fmaxf(v, 0.f);
    }
    __syncthreads();
    if (tid < 15) {
        float v = b5[tid];
        for (int q = 0; q < 10; q++) v = fmaf(s_ha[q], W5[tid * 10 + q], v);
        s_ll[tid] = v;
    }
    __syncthreads();

    if (tid < 15) {
        int c = tid / NMIX, m = tid % NMIX;
        float wacc = 0.f;
        for (int s = 0; s < NS; s++) {
            float z[NMIX], zmax = -1e30f;
#pragma unroll
            for (int mp = 0; mp < NMIX; mp++) {
                float u = unif[((b * NS + s) * NCH + c) * NMIX + mp];
                float g = -logf(-logf(u + 1e-20f));
                z[mp] = (g + s_ll[c * NMIX + mp]) * 10.0f;
                zmax = fmaxf(zmax, z[mp]);
            }
            float denom = 0.f, em = 0.f;
#pragma unroll
            for (int mp = 0; mp < NMIX; mp++) {
                float e = __expf(z[mp] - zmax);
                denom += e;
                if (mp == m) em = e;
            }
            wacc += em / denom;
        }
        g_w[(b * NCH + c) * NMIX + m] = wacc / (float)NS;
    }
}

// ============ Kernel 3: weighted output (j-in-regs, i-tiled) ============
// grid = (3 j-segs, 24 i-tiles, 8 b), block = 256. One wave (576 blocks, 4/SM).
#define ITILE 32
__global__ void __launch_bounds__(256, 4) k3_weighted(
        const float* __restrict__ likerr,
        const float* __restrict__ inv_std,
        float* __restrict__ out) {
    __shared__ float  s_xi[ITILE * NCH];          // [ii][c]
    __shared__ float2 s_w2[ITILE * NCH * NMIX];   // [ii][c][m] = (w*cos_i, w*sin_i)

    int seg = blockIdx.x;
    int it  = blockIdx.y;
    int b   = blockIdx.z;
    int tid = threadIdx.x;
    int j   = seg * 256 + tid;
    int i0  = it * ITILE;

    // ---- j-side into registers ----
    float xj[NCH], cj[NCH][NMIX], sj[NCH][NMIX];
#pragma unroll
    for (int c = 0; c < NCH; c++) {
        int bc = b * NCH + c;
        xj[c] = g_xr[bc * ND + j];
#pragma unroll
        for (int m = 0; m < NMIX; m++) {
            float2 cs = g_tab[(bc * NMIX + m) * ND + j];
            cj[c][m] = cs.x; sj[c][m] = cs.y;
        }
    }
    float am[NMIX];
#pragma unroll
    for (int m = 0; m < NMIX; m++) {
        float iv = __ldg(&inv_std[m]);
        am[m] = CEXP * iv * iv;
    }
    float dg[NCH];
#pragma unroll
    for (int c = 0; c < NCH; c++) {
        float lv = fminf(fmaxf(__ldg(&likerr[c]), 0.1f), 1.0f);
        dg[c] = ZITTER + lv * lv;
    }

    // ---- stage i-side tile ----
    for (int t = tid; t < ITILE * NCH * NMIX; t += 256) {
        int ii = t / (NCH * NMIX);
        int cm = t % (NCH * NMIX);
        int c = cm / NMIX, m = cm % NMIX;
        int bc = b * NCH + c;
        float2 cs = g_tab[(bc * NMIX + m) * ND + (i0 + ii)];
        float ww = g_w[bc * NMIX + m];
        s_w2[t] = make_float2(ww * cs.x, ww * cs.y);
    }
    for (int t = tid; t < ITILE * NCH; t += 256) {
        int ii = t / NCH, c = t % NCH;
        s_xi[t] = g_xr[(b * NCH + c) * ND + (i0 + ii)];
    }
    __syncthreads();

    // ---- main loop over i tile ----
#pragma unroll 2
    for (int ii = 0; ii < ITILE; ii++) {
        int i = i0 + ii;
        float res[NCH];
#pragma unroll
        for (int c = 0; c < NCH; c++) {
            float d = s_xi[ii * NCH + c] - xj[c];
            float t2 = d * d;
            float acc = 0.f;
            int base = (ii * NCH + c) * NMIX;
#pragma unroll
            for (int m = 0; m < NMIX; m++) {
                float2 w2 = s_w2[base + m];
                float e = ex2f(am[m] * t2);
                float p = fmaf(w2.y, sj[c][m], w2.x * cj[c][m]);
                acc = fmaf(e, p, acc);
            }
            if (j == i) acc += dg[c];
            res[c] = acc;
        }
        long long obase = (((long long)(b * ND + i)) * ND + j) * NCH;
        out[obase + 0] = res[0];
        out[obase + 1] = res[1];
        out[obase + 2] = res[2];
    }
}

// ---------------- launch ----------------
extern "C" void kernel_launch(void* const* d_in, const int* in_sizes, int n_in,
                              void* d_out, int out_size) {
    const float* xc      = (const float*)d_in[0];
    const float* yc      = (const float*)d_in[1];
    const float* mu      = (const float*)d_in[2];
    const float* inv_std = (const float*)d_in[3];
    const float* likerr  = (const float*)d_in[4];
    const float* unif    = (const float*)d_in[5];
    const float* W1 = (const float*)d_in[6];
    const float* b1 = (const float*)d_in[7];
    const float* W2 = (const float*)d_in[8];
    const float* b2 = (const float*)d_in[9];
    const float* W3 = (const float*)d_in[10];
    const float* b3 = (const float*)d_in[11];
    const float* W4 = (const float*)d_in[12];
    const float* b4 = (const float*)d_in[13];
    const float* W5 = (const float*)d_in[14];
    const float* b5 = (const float*)d_in[15];
    float* out = (float*)d_out;

    k0_tables<<<NB * NCH, ND>>>(xc, yc, mu);
    k1_feature<<<dim3(6 * NSEG, NCH, NB), 128>>>(inv_std);
    k2_mlp<<<NB, 256>>>(yc, unif, W1, b1, W2, b2, W3, b3, W4, b4, W5, b5);
    k3_weighted<<<dim3(3, ND / ITILE, NB), 256>>>(likerr, inv_std, out);
}

// round 4
// speedup vs baseline: 1.1083x; 1.1083x over previous
#include <cuda_runtime.h>
#include <math.h>

// ---------------- problem constants ----------------
#define NB   8
#define ND   768
#define NCH  3
#define NMIX 5
#define NS   10
#define H    10
#define PI2f 6.2831853071795864769f
// C = -0.5*(2pi)^2 * log2(e)  (fold exp->exp2)
#define CEXP (-28.47813296f)
#define ZITTER 1e-4f

// ---------------- device scratch ----------------
__device__ float2 g_tab[NB * NCH * NMIX * ND];   // (cos,sin)(2pi*mu_m*x_j)
__device__ float2 g_tabY[NB * NCH * NMIX * ND];  // y-premultiplied
__device__ float  g_xr[NB * NCH * ND];
#define NSEG 4
#define JSEG 192
__device__ float  g_fpart[NSEG][NB * ND * NCH * NMIX];
__device__ float  g_w[NB * NCH * NMIX];

__device__ __forceinline__ float ex2f(float x) {
    float y;
    asm("ex2.approx.ftz.f32 %0, %1;" : "=f"(y) : "f"(x));
    return y;
}

// ============ Kernel 0: trig tables (+ y-premultiplied) ============
__global__ void k0_tables(const float* __restrict__ xc,
                          const float* __restrict__ yc,
                          const float* __restrict__ mu) {
    int bc = blockIdx.x;
    int b = bc / NCH, c = bc % NCH;
    int j = threadIdx.x;
    float x = xc[(b * ND + j) * NCH + c];
    float y = yc[(b * ND + j) * NCH + c];
    g_xr[bc * ND + j] = x;
#pragma unroll
    for (int m = 0; m < NMIX; m++) {
        float s, co;
        sincosf(PI2f * mu[m] * x, &s, &co);
        g_tab [(bc * NMIX + m) * ND + j] = make_float2(co, s);
        g_tabY[(bc * NMIX + m) * ND + j] = make_float2(co * y, s * y);
    }
}

// ============ Kernel 1: feature partials ============
// grid: x = 6 i-tiles * 4 j-segs, y = c, z = b; block = 128 (576 blocks)
__global__ void k1_feature(const float* __restrict__ inv_std) {
    __shared__ float  x_sh[JSEG];
    __shared__ float2 tabY[NMIX * JSEG];

    int seg  = blockIdx.x & 3;
    int tile = blockIdx.x >> 2;
    int c = blockIdx.y, b = blockIdx.z;
    int bc = b * NCH + c;
    int tid = threadIdx.x;
    int j0 = seg * JSEG;

    for (int t = tid; t < JSEG; t += 128)
        x_sh[t] = g_xr[bc * ND + j0 + t];
    for (int idx = tid; idx < NMIX * JSEG; idx += 128) {
        int m = idx / JSEG, jl = idx % JSEG;
        tabY[idx] = g_tabY[(bc * NMIX + m) * ND + j0 + jl];
    }
    __syncthreads();

    int i = tile * 128 + tid;
    float xi = g_xr[bc * ND + i];
    float ci[NMIX], si[NMIX], am[NMIX], acc[NMIX];
#pragma unroll
    for (int m = 0; m < NMIX; m++) {
        float2 cs = g_tab[(bc * NMIX + m) * ND + i];
        ci[m] = cs.x; si[m] = cs.y;
        float iv = __ldg(&inv_std[m]);
        am[m] = CEXP * iv * iv;
        acc[m] = 0.f;
    }

#pragma unroll 4
    for (int jl = 0; jl < JSEG; jl++) {
        float d = xi - x_sh[jl];
        float t = d * d;
#pragma unroll
        for (int m = 0; m < NMIX; m++) {
            float2 cy = tabY[m * JSEG + jl];
            float e = ex2f(am[m] * t);
            float p = fmaf(si[m], cy.y, ci[m] * cy.x);
            acc[m] = fmaf(e, p, acc[m]);
        }
    }

    int base = ((b * ND + i) * NCH + c) * NMIX;
#pragma unroll
    for (int m = 0; m < NMIX; m++)
        g_fpart[seg][base + m] = acc[m];
}

// ============ Kernel 2: MLP + Gumbel softmax -> mixture weights ============
__global__ void k2_mlp(const float* __restrict__ yc,
                       const float* __restrict__ unif,
                       const float* __restrict__ W1, const float* __restrict__ b1,
                       const float* __restrict__ W2, const float* __restrict__ b2,
                       const float* __restrict__ W3, const float* __restrict__ b3,
                       const float* __restrict__ W4, const float* __restrict__ b4,
                       const float* __restrict__ W5, const float* __restrict__ b5) {
    __shared__ float s_part[256 * 30];
    __shared__ float s_r8[8 * 30];
    __shared__ float s_W1[60], s_b1[10];
    __shared__ float s_hm[30];
    __shared__ float s_ha[10], s_hb[10];
    __shared__ float s_ll[15];

    int b = blockIdx.x;
    int tid = threadIdx.x;
    if (tid < 60) s_W1[tid] = W1[tid];
    if (tid < 10) s_b1[tid] = b1[tid];
    __syncthreads();

    float acc30[30];
#pragma unroll
    for (int q = 0; q < 30; q++) acc30[q] = 0.f;

    for (int rep = 0; rep < 3; rep++) {
        int i = tid + rep * 256;
#pragma unroll
        for (int c = 0; c < NCH; c++) {
            int base = ((b * ND + i) * NCH + c) * NMIX;
            float y = yc[(b * ND + i) * NCH + c];
            float tif[6];
#pragma unroll
            for (int m = 0; m < NMIX; m++) {
                float f = ZITTER * y;
#pragma unroll
                for (int s = 0; s < NSEG; s++) f += g_fpart[s][base + m];
                tif[m] = f;
            }
            tif[5] = y;
#pragma unroll
            for (int k = 0; k < H; k++) {
                float h = s_b1[k];
#pragma unroll
                for (int q = 0; q < 6; q++) h = fmaf(tif[q], s_W1[k * 6 + q], h);
                acc30[c * H + k] += fmaxf(h, 0.f);
            }
        }
    }
#pragma unroll
    for (int q = 0; q < 30; q++) s_part[tid * 30 + q] = acc30[q];
    __syncthreads();

    // parallel two-stage mean reduction: 240 threads, 32 adds each
    if (tid < 240) {
        int q = tid >> 3, p = tid & 7;
        float s = 0.f;
        int t0 = p * 32;
#pragma unroll 4
        for (int t = t0; t < t0 + 32; t++) s += s_part[t * 30 + q];
        s_r8[p * 30 + q] = s;
    }
    __syncthreads();
    if (tid < 30) {
        float s = 0.f;
#pragma unroll
        for (int p = 0; p < 8; p++) s += s_r8[p * 30 + tid];
        s_hm[tid] = s / (float)ND;
    }
    __syncthreads();

    if (tid < 10) {
        float v = b2[tid];
        for (int q = 0; q < 30; q++) v = fmaf(s_hm[q], W2[tid * 30 + q], v);
        s_ha[tid] = fmaxf(v, 0.f);
    }
    __syncthreads();
    if (tid < 10) {
        float v = b3[tid];
        for (int q = 0; q < 10; q++) v = fmaf(s_ha[q], W3[tid * 10 + q], v);
        s_hb[tid] = fmaxf(v, 0.f);
    }
    __syncthreads();
    if (tid < 10) {
        float v = b4[tid];
        for (int q = 0; q < 10; q++) v = fmaf(s_hb[q], W4[tid * 10 + q], v);
        s_ha[tid] = fmaxf(v, 0.f);
    }
    __syncthreads();
    if (tid < 15) {
        float v = b5[tid];
        for (int q = 0; q < 10; q++) v = fmaf(s_ha[q], W5[tid * 10 + q], v);
        s_ll[tid] = v;
    }
    __syncthreads();

    if (tid < 15) {
        int c = tid / NMIX, m = tid % NMIX;
        float wacc = 0.f;
        for (int s = 0; s < NS; s++) {
            float z[NMIX], zmax = -1e30f;
#pragma unroll
            for (int mp = 0; mp < NMIX; mp++) {
                float u = unif[((b * NS + s) * NCH + c) * NMIX + mp];
                float g = -logf(-logf(u + 1e-20f));
                z[mp] = (g + s_ll[c * NMIX + mp]) * 10.0f;
                zmax = fmaxf(zmax, z[mp]);
            }
            float denom = 0.f, em = 0.f;
#pragma unroll
            for (int mp = 0; mp < NMIX; mp++) {
                float e = __expf(z[mp] - zmax);
                denom += e;
                if (mp == m) em = e;
            }
            wacc += em / denom;
        }
        g_w[(b * NCH + c) * NMIX + m] = wacc / (float)NS;
    }
}

// ============ Kernel 3: weighted output (j-in-regs, i-tiled) ============
// grid = (3 j-segs, 24 i-tiles, 8 b), block = 256. One wave (576 blocks, 4/SM).
#define ITILE 32
__global__ void __launch_bounds__(256, 4) k3_weighted(
        const float* __restrict__ likerr,
        const float* __restrict__ inv_std,
        float* __restrict__ out) {
    __shared__ float  s_xi[ITILE * NCH];          // [ii][c]
    __shared__ float2 s_w2[ITILE * NCH * NMIX];   // [ii][c][m] = (w*cos_i, w*sin_i)

    int seg = blockIdx.x;
    int it  = blockIdx.y;
    int b   = blockIdx.z;
    int tid = threadIdx.x;
    int j   = seg * 256 + tid;
    int i0  = it * ITILE;

    // ---- j-side into registers ----
    float xj[NCH], cj[NCH][NMIX], sj[NCH][NMIX];
#pragma unroll
    for (int c = 0; c < NCH; c++) {
        int bc = b * NCH + c;
        xj[c] = g_xr[bc * ND + j];
#pragma unroll
        for (int m = 0; m < NMIX; m++) {
            float2 cs = g_tab[(bc * NMIX + m) * ND + j];
            cj[c][m] = cs.x; sj[c][m] = cs.y;
        }
    }
    float am[NMIX];
#pragma unroll
    for (int m = 0; m < NMIX; m++) {
        float iv = __ldg(&inv_std[m]);
        am[m] = CEXP * iv * iv;
    }
    float dg[NCH];
#pragma unroll
    for (int c = 0; c < NCH; c++) {
        float lv = fminf(fmaxf(__ldg(&likerr[c]), 0.1f), 1.0f);
        dg[c] = ZITTER + lv * lv;
    }

    // ---- stage i-side tile ----
    for (int t = tid; t < ITILE * NCH * NMIX; t += 256) {
        int ii = t / (NCH * NMIX);
        int cm = t % (NCH * NMIX);
        int c = cm / NMIX, m = cm % NMIX;
        int bc = b * NCH + c;
        float2 cs = g_tab[(bc * NMIX + m) * ND + (i0 + ii)];
        float ww = g_w[bc * NMIX + m];
        s_w2[t] = make_float2(ww * cs.x, ww * cs.y);
    }
    for (int t = tid; t < ITILE * NCH; t += 256) {
        int ii = t / NCH, c = t % NCH;
        s_xi[t] = g_xr[(b * NCH + c) * ND + (i0 + ii)];
    }
    __syncthreads();

    // ---- main loop over i tile ----
#pragma unroll 2
    for (int ii = 0; ii < ITILE; ii++) {
        int i = i0 + ii;
        float res[NCH];
#pragma unroll
        for (int c = 0; c < NCH; c++) {
            float d = s_xi[ii * NCH + c] - xj[c];
            float t2 = d * d;
            float acc = 0.f;
            int base = (ii * NCH + c) * NMIX;
#pragma unroll
            for (int m = 0; m < NMIX; m++) {
                float2 w2 = s_w2[base + m];
                float e = ex2f(am[m] * t2);
                float p = fmaf(w2.y, sj[c][m], w2.x * cj[c][m]);
                acc = fmaf(e, p, acc);
            }
            if (j == i) acc += dg[c];
            res[c] = acc;
        }
        long long obase = (((long long)(b * ND + i)) * ND + j) * NCH;
        out[obase + 0] = res[0];
        out[obase + 1] = res[1];
        out[obase + 2] = res[2];
    }
}

// ---------------- launch ----------------
extern "C" void kernel_launch(void* const* d_in, const int* in_sizes, int n_in,
                              void* d_out, int out_size) {
    const float* xc      = (const float*)d_in[0];
    const float* yc      = (const float*)d_in[1];
    const float* mu      = (const float*)d_in[2];
    const float* inv_std = (const float*)d_in[3];
    const float* likerr  = (const float*)d_in[4];
    const float* unif    = (const float*)d_in[5];
    const float* W1 = (const float*)d_in[6];
    const float* b1 = (const float*)d_in[7];
    const float* W2 = (const float*)d_in[8];
    const float* b2 = (const float*)d_in[9];
    const float* W3 = (const float*)d_in[10];
    const float* b3 = (const float*)d_in[11];
    const float* W4 = (const float*)d_in[12];
    const float* b4 = (const float*)d_in[13];
    const float* W5 = (const float*)d_in[14];
    const float* b5 = (const float*)d_in[15];
    float* out = (float*)d_out;

    k0_tables<<<NB * NCH, ND>>>(xc, yc, mu);
    k1_feature<<<dim3(6 * NSEG, NCH, NB), 128>>>(inv_std);
    k2_mlp<<<NB, 256>>>(yc, unif, W1, b1, W2, b2, W3, b3, W4, b4, W5, b5);
    k3_weighted<<<dim3(3, ND / ITILE, NB), 256>>>(likerr, inv_std, out);
}